// round 3
// baseline (speedup 1.0000x reference)
#include <cuda_runtime.h>
#include <cuda_bf16.h>
#include <math.h>

#define VOCAB 32000
#define HID   512
#define EMB   256
#define NB    256
#define LEN   512

// Scratch (static device allocations are allowed; runtime allocs are not).
__device__ float g_P[VOCAB * HID];        // P = emb @ Wxh^T + Wxh_b   (65.5 MB)
__device__ float g_h[2][NB * HID];        // ping-pong hidden state

// ---------------------------------------------------------------------------
// proj_kernel: g_P[v,h] = sum_e emb[v,e] * Wxh_w[h,e] + Wxh_b[h]
// 32x32 output tile per block, 256 threads = 8 k-groups x 32 lanes,
// 4x8 register micro-tile per lane, k-split reduced through SMEM.
// ---------------------------------------------------------------------------
__global__ void proj_kernel(const float* __restrict__ emb,
                            const float* __restrict__ Wxh_w,
                            const float* __restrict__ Wxh_b) {
    const int K   = EMB;
    const int STR = EMB + 4;          // padded row stride (floats)
    extern __shared__ float sm[];
    float* As  = sm;                  // 32 x STR  (emb rows)
    float* Ws  = sm + 32 * STR;       // 32 x STR  (Wxh rows)
    float* red = sm + 64 * STR;       // 8 x 32 x 36

    const int tid = threadIdx.x;
    const int v0  = blockIdx.x * 32;
    const int h0  = blockIdx.y * 32;

    // Load both 32xK tiles (float4, coalesced)
    const int NV4 = 32 * (K / 4);
    for (int idx = tid; idx < NV4; idx += 256) {
        int r  = idx / (K / 4);
        int c4 = (idx % (K / 4)) * 4;
        *(float4*)&As[r * STR + c4] = *(const float4*)&emb[(size_t)(v0 + r) * K + c4];
        *(float4*)&Ws[r * STR + c4] = *(const float4*)&Wxh_w[(size_t)(h0 + r) * K + c4];
    }
    __syncthreads();

    const int lane = tid & 31, kg = tid >> 5;
    const int ln = lane & 7, lh = lane >> 3;
    const int kb = kg * (K / 8);

    float acc[4][8];
#pragma unroll
    for (int i = 0; i < 4; i++)
#pragma unroll
        for (int j = 0; j < 8; j++) acc[i][j] = 0.f;

#pragma unroll 4
    for (int kk = 0; kk < K / 8; kk += 4) {
        float4 av[4], wv[8];
#pragma unroll
        for (int i = 0; i < 4; i++)
            av[i] = *(const float4*)&As[(ln + 8 * i) * STR + kb + kk];
#pragma unroll
        for (int j = 0; j < 8; j++)
            wv[j] = *(const float4*)&Ws[(lh + 4 * j) * STR + kb + kk];
#pragma unroll
        for (int i = 0; i < 4; i++)
#pragma unroll
            for (int j = 0; j < 8; j++)
                acc[i][j] += av[i].x * wv[j].x + av[i].y * wv[j].y +
                             av[i].z * wv[j].z + av[i].w * wv[j].w;
    }

    // k-split partials -> SMEM (conflict-free: bank = (4*ln + lh) distinct)
#pragma unroll
    for (int i = 0; i < 4; i++)
#pragma unroll
        for (int j = 0; j < 8; j++)
            red[kg * 1152 + (ln + 8 * i) * 36 + (lh + 4 * j)] = acc[i][j];
    __syncthreads();

    // reduce 8 partials, add bias, store
    const int o_n = tid >> 3, o_h = (tid & 7) * 4;
    float4 s = make_float4(0.f, 0.f, 0.f, 0.f);
#pragma unroll
    for (int g = 0; g < 8; g++) {
        float4 p = *(const float4*)&red[g * 1152 + o_n * 36 + o_h];
        s.x += p.x; s.y += p.y; s.z += p.z; s.w += p.w;
    }
    float4 b4 = *(const float4*)&Wxh_b[h0 + o_h];
    s.x += b4.x; s.y += b4.y; s.z += b4.z; s.w += b4.w;
    *(float4*)&g_P[(size_t)(v0 + o_n) * HID + h0 + o_h] = s;
}

// ---------------------------------------------------------------------------
// step0: h_1 = tanh(Whh_b + P[X[:,0],:])   (h_0 == 0, skip the GEMM)
// ---------------------------------------------------------------------------
__global__ void step0_kernel(const int* __restrict__ X,
                             const float* __restrict__ Whh_b) {
    int idx = blockIdx.x * 256 + threadIdx.x;   // over NB*HID
    int n = idx >> 9, h = idx & (HID - 1);
    int xid = X[n * LEN];                       // t = 0
    g_h[0][idx] = tanhf(Whh_b[h] + g_P[(size_t)xid * HID + h]);
}

// ---------------------------------------------------------------------------
// step_kernel (t = 1..511):
//   h_out = tanh(h_in @ Whh^T + Whh_b + P[X[:,t],:])
// Same 32x32 tile / 8-way k-split structure as proj (K = 512).
// h_in = g_h[(t+1)&1]; h_out = d_out on the last step, else g_h[t&1].
// ---------------------------------------------------------------------------
__global__ void step_kernel(const int* __restrict__ X,
                            const float* __restrict__ Whh_w,
                            const float* __restrict__ Whh_b,
                            int t, float* __restrict__ final_out) {
    const int K   = HID;
    const int STR = HID + 4;
    extern __shared__ float sm[];
    float* Hs  = sm;                  // 32 x STR  (h_in rows)
    float* Ws  = sm + 32 * STR;       // 32 x STR  (Whh rows)
    float* red = sm + 64 * STR;       // 8 x 32 x 36

    const float* __restrict__ h_in = g_h[(t + 1) & 1];
    float* __restrict__ h_out = final_out ? final_out : g_h[t & 1];

    const int tid = threadIdx.x;
    const int n0  = blockIdx.x * 32;
    const int h0  = blockIdx.y * 32;

    const int NV4 = 32 * (K / 4);
    for (int idx = tid; idx < NV4; idx += 256) {
        int r  = idx / (K / 4);
        int c4 = (idx % (K / 4)) * 4;
        *(float4*)&Hs[r * STR + c4] = *(const float4*)&h_in[(size_t)(n0 + r) * K + c4];
        *(float4*)&Ws[r * STR + c4] = *(const float4*)&Whh_w[(size_t)(h0 + r) * K + c4];
    }
    __syncthreads();

    const int lane = tid & 31, kg = tid >> 5;
    const int ln = lane & 7, lh = lane >> 3;
    const int kb = kg * (K / 8);      // 64-wide k slice per group

    float acc[4][8];
#pragma unroll
    for (int i = 0; i < 4; i++)
#pragma unroll
        for (int j = 0; j < 8; j++) acc[i][j] = 0.f;

#pragma unroll 4
    for (int kk = 0; kk < K / 8; kk += 4) {
        float4 hv[4], wv[8];
#pragma unroll
        for (int i = 0; i < 4; i++)
            hv[i] = *(const float4*)&Hs[(ln + 8 * i) * STR + kb + kk];
#pragma unroll
        for (int j = 0; j < 8; j++)
            wv[j] = *(const float4*)&Ws[(lh + 4 * j) * STR + kb + kk];
#pragma unroll
        for (int i = 0; i < 4; i++)
#pragma unroll
            for (int j = 0; j < 8; j++)
                acc[i][j] += hv[i].x * wv[j].x + hv[i].y * wv[j].y +
                             hv[i].z * wv[j].z + hv[i].w * wv[j].w;
    }

#pragma unroll
    for (int i = 0; i < 4; i++)
#pragma unroll
        for (int j = 0; j < 8; j++)
            red[kg * 1152 + (ln + 8 * i) * 36 + (lh + 4 * j)] = acc[i][j];
    __syncthreads();

    const int o_n = tid >> 3, o_h = (tid & 7) * 4;
    float4 s = make_float4(0.f, 0.f, 0.f, 0.f);
#pragma unroll
    for (int g = 0; g < 8; g++) {
        float4 p = *(const float4*)&red[g * 1152 + o_n * 36 + o_h];
        s.x += p.x; s.y += p.y; s.z += p.z; s.w += p.w;
    }

    const int n   = n0 + o_n;
    const int xid = X[n * LEN + t];
    float4 xp = *(const float4*)&g_P[(size_t)xid * HID + h0 + o_h];
    float4 b4 = *(const float4*)&Whh_b[h0 + o_h];
    float4 o;
    o.x = tanhf(s.x + b4.x + xp.x);
    o.y = tanhf(s.y + b4.y + xp.y);
    o.z = tanhf(s.z + b4.z + xp.z);
    o.w = tanhf(s.w + b4.w + xp.w);
    *(float4*)&h_out[(size_t)n * HID + h0 + o_h] = o;
}

// ---------------------------------------------------------------------------
extern "C" void kernel_launch(void* const* d_in, const int* in_sizes, int n_in,
                              void* d_out, int out_size) {
    const int*   X     = (const int*)d_in[0];
    const float* emb   = (const float*)d_in[1];
    const float* Whh_w = (const float*)d_in[2];
    const float* Whh_b = (const float*)d_in[3];
    const float* Wxh_w = (const float*)d_in[4];
    const float* Wxh_b = (const float*)d_in[5];
    float* out = (float*)d_out;

    const size_t sm_proj = (size_t)(64 * (EMB + 4) + 8 * 32 * 36) * sizeof(float); // ~101 KB
    const size_t sm_step = (size_t)(64 * (HID + 4) + 8 * 32 * 36) * sizeof(float); // ~165 KB
    cudaFuncSetAttribute(proj_kernel, cudaFuncAttributeMaxDynamicSharedMemorySize, (int)sm_proj);
    cudaFuncSetAttribute(step_kernel, cudaFuncAttributeMaxDynamicSharedMemorySize, (int)sm_step);

    // 1) P = emb @ Wxh^T + Wxh_b
    proj_kernel<<<dim3(VOCAB / 32, HID / 32), 256, sm_proj>>>(emb, Wxh_w, Wxh_b);

    // 2) t = 0 (h0 == 0)
    step0_kernel<<<(NB * HID) / 256, 256>>>(X, Whh_b);

    // 3) t = 1 .. 511
    for (int t = 1; t < LEN; t++) {
        float* fin = (t == LEN - 1) ? out : nullptr;
        step_kernel<<<dim3(NB / 32, HID / 32), 256, sm_step>>>(X, Whh_w, Whh_b, t, fin);
    }
}

// round 5
// speedup vs baseline: 1.3001x; 1.3001x over previous
#include <cuda_runtime.h>
#include <cuda_bf16.h>
#include <stdint.h>
#include <math.h>

#define VOCAB 32000
#define HID   512
#define EMB   256
#define NB    256
#define LEN   512
#define GRID  128
#define NTHR  512

// Scratch (static device allocations are allowed; runtime allocs are not).
__device__ float g_P[VOCAB * HID];        // P = emb @ Wxh^T + Wxh_b   (65.5 MB)
__device__ float g_h[2][NB * HID];        // ping-pong hidden state
__device__ unsigned g_bar_count;          // grid barrier arrivals
__device__ unsigned g_bar_gen;            // grid barrier generation (monotonic)

// Packed fp32x2 FMA (B300 packed pipe; ptxas never emits this from C++).
__device__ __forceinline__ unsigned long long ffma2(unsigned long long a,
                                                    unsigned long long b,
                                                    unsigned long long c) {
    unsigned long long d;
    asm("fma.rn.f32x2 %0, %1, %2, %3;" : "=l"(d) : "l"(a), "l"(b), "l"(c));
    return d;
}

// ---------------------------------------------------------------------------
// proj_kernel: g_P[v,h] = sum_e emb[v,e] * Wxh_w[h,e] + Wxh_b[h]
// 32x32 output tile per block, 256 threads = 8 k-groups x 32 lanes,
// 4x8 register micro-tile per lane, k-split reduced through SMEM.
// ---------------------------------------------------------------------------
__global__ void proj_kernel(const float* __restrict__ emb,
                            const float* __restrict__ Wxh_w,
                            const float* __restrict__ Wxh_b) {
    const int K   = EMB;
    const int STR = EMB + 4;
    extern __shared__ float sm[];
    float* As  = sm;
    float* Ws  = sm + 32 * STR;
    float* red = sm + 64 * STR;

    const int tid = threadIdx.x;
    const int v0  = blockIdx.x * 32;
    const int h0  = blockIdx.y * 32;

    const int NV4 = 32 * (K / 4);
    for (int idx = tid; idx < NV4; idx += 256) {
        int r  = idx / (K / 4);
        int c4 = (idx % (K / 4)) * 4;
        *(float4*)&As[r * STR + c4] = *(const float4*)&emb[(size_t)(v0 + r) * K + c4];
        *(float4*)&Ws[r * STR + c4] = *(const float4*)&Wxh_w[(size_t)(h0 + r) * K + c4];
    }
    __syncthreads();

    const int lane = tid & 31, kg = tid >> 5;
    const int ln = lane & 7, lh = lane >> 3;
    const int kb = kg * (K / 8);

    float acc[4][8];
#pragma unroll
    for (int i = 0; i < 4; i++)
#pragma unroll
        for (int j = 0; j < 8; j++) acc[i][j] = 0.f;

#pragma unroll 4
    for (int kk = 0; kk < K / 8; kk += 4) {
        float4 av[4], wv[8];
#pragma unroll
        for (int i = 0; i < 4; i++)
            av[i] = *(const float4*)&As[(ln + 8 * i) * STR + kb + kk];
#pragma unroll
        for (int j = 0; j < 8; j++)
            wv[j] = *(const float4*)&Ws[(lh + 4 * j) * STR + kb + kk];
#pragma unroll
        for (int i = 0; i < 4; i++)
#pragma unroll
            for (int j = 0; j < 8; j++)
                acc[i][j] += av[i].x * wv[j].x + av[i].y * wv[j].y +
                             av[i].z * wv[j].z + av[i].w * wv[j].w;
    }

#pragma unroll
    for (int i = 0; i < 4; i++)
#pragma unroll
        for (int j = 0; j < 8; j++)
            red[kg * 1152 + (ln + 8 * i) * 36 + (lh + 4 * j)] = acc[i][j];
    __syncthreads();

    const int o_n = tid >> 3, o_h = (tid & 7) * 4;
    float4 s = make_float4(0.f, 0.f, 0.f, 0.f);
#pragma unroll
    for (int g = 0; g < 8; g++) {
        float4 p = *(const float4*)&red[g * 1152 + o_n * 36 + o_h];
        s.x += p.x; s.y += p.y; s.z += p.z; s.w += p.w;
    }
    float4 b4 = *(const float4*)&Wxh_b[h0 + o_h];
    s.x += b4.x; s.y += b4.y; s.z += b4.z; s.w += b4.w;
    *(float4*)&g_P[(size_t)(v0 + o_n) * HID + h0 + o_h] = s;
}

// ---------------------------------------------------------------------------
// rnn_kernel: ONE persistent launch doing all 512 timesteps.
//   128 blocks (one per SM, all resident), 512 threads.
//   Block (b): output tile n0 = (b>>4)*32, h0 = (b&15)*32.
//   warp w (0..15) = k-group (k slice of 32), lane = h-row within tile.
//   Whh slice lives in REGISTERS for the whole kernel (16 x u64 per thread).
//   Per step: cp.async.cg own h slice (L1-bypass: ping-pong reuse within one
//   launch makes L1 stale), FFMA2 compute, SMEM k-reduction, fused epilogue,
//   hand-rolled grid barrier (release/acquire on g_bar_gen).
// ---------------------------------------------------------------------------
__global__ void __launch_bounds__(NTHR, 1) rnn_kernel(
    const int*   __restrict__ X,
    const float* __restrict__ Whh_w,
    const float* __restrict__ Whh_b,
    float*       __restrict__ out)
{
    extern __shared__ float sm[];
    float* sm_h   = sm;                 // 16 warps x 32n x 32k  (64 KB)
    float* sm_red = sm + 16 * 1024;     // 16 kg  x 32n x 32h    (64 KB)

    const int tid  = threadIdx.x;
    const int w    = tid >> 5;          // k-group / warp id
    const int lane = tid & 31;          // h-row within tile
    const int b    = blockIdx.x;
    const int n0   = (b >> 4) * 32;
    const int h0   = (b & 15) * 32;

    // --- persistent weight registers: W[h0+lane][w*32 .. w*32+31] -----------
    unsigned long long w2[16];
    {
        const ulonglong2* wp =
            (const ulonglong2*)&Whh_w[(size_t)(h0 + lane) * HID + w * 32];
#pragma unroll
        for (int i = 0; i < 8; i++) {
            ulonglong2 v = wp[i];
            w2[2 * i] = v.x; w2[2 * i + 1] = v.y;
        }
    }
    const float bb = Whh_b[h0 + lane];

    unsigned gen0 = 0;
    if (tid == 0)
        asm volatile("ld.acquire.gpu.u32 %0, [%1];" : "=r"(gen0) : "l"(&g_bar_gen));

    unsigned int smem_w_base;
    {
        unsigned int a;
        asm("{ .reg .u64 t; cvta.to.shared.u64 t, %1; cvt.u32.u64 %0, t; }"
            : "=r"(a) : "l"(sm_h + w * 1024));
        smem_w_base = a;
    }

    const int myn1 = n0 + w;        // output row for o1 = tid
    const int myn2 = n0 + w + 16;   // output row for o2 = tid + 512

    for (int t = 0; t < LEN; t++) {
        const float* hin = (t & 1) ? g_h[0] : g_h[1];   // read (t-1)&1
        float* dst = (t == LEN - 1) ? out : ((t & 1) ? g_h[1] : g_h[0]);

        float s1 = 0.f, s2 = 0.f;

        if (t > 0) {
            // --- async load of this warp's 32n x 32k h slice (L1 bypass) ----
#pragma unroll
            for (int i = 0; i < 8; i++) {
                int c  = i * 32 + lane;     // 16B chunk id within slice
                int n  = c >> 3;
                int kq = c & 7;
                const float* src = &hin[(size_t)(n0 + n) * HID + w * 32 + kq * 4];
                asm volatile("cp.async.cg.shared.global [%0], [%1], 16;"
                             :: "r"(smem_w_base + c * 16), "l"(src) : "memory");
            }
            asm volatile("cp.async.commit_group;" ::: "memory");
            asm volatile("cp.async.wait_group 0;" ::: "memory");
            __syncthreads();

            // --- compute: two halves of 16 n (keeps regs under 128) ---------
#pragma unroll
            for (int half = 0; half < 2; half++) {
                unsigned long long acc[16];
#pragma unroll
                for (int n = 0; n < 16; n++) acc[n] = 0ULL;
                const float* hp = sm_h + w * 1024 + half * 16 * 32;
#pragma unroll
                for (int n = 0; n < 16; n += 2) {
                    const ulonglong2* r0 = (const ulonglong2*)(hp + n * 32);
                    const ulonglong2* r1 = (const ulonglong2*)(hp + (n + 1) * 32);
                    unsigned long long a0 = acc[n], a1 = acc[n + 1];
#pragma unroll
                    for (int q = 0; q < 8; q++) {
                        ulonglong2 v0 = r0[q], v1 = r1[q];
                        a0 = ffma2(v0.x, w2[2 * q],     a0);
                        a0 = ffma2(v0.y, w2[2 * q + 1], a0);
                        a1 = ffma2(v1.x, w2[2 * q],     a1);
                        a1 = ffma2(v1.y, w2[2 * q + 1], a1);
                    }
                    acc[n] = a0; acc[n + 1] = a1;
                }
#pragma unroll
                for (int n = 0; n < 16; n++) {
                    float2 f = *(float2*)&acc[n];
                    sm_red[w * 1024 + (half * 16 + n) * 32 + lane] = f.x + f.y;
                }
            }
            __syncthreads();

            // --- k-group reduction for outputs o1 = tid, o2 = tid + 512 -----
            float sa = 0.f, sb = 0.f;
#pragma unroll
            for (int g = 0; g < 16; g += 2) {
                sa += sm_red[g * 1024 + tid];
                sb += sm_red[(g + 1) * 1024 + tid];
            }
            s1 = sa + sb;
            sa = 0.f; sb = 0.f;
#pragma unroll
            for (int g = 0; g < 16; g += 2) {
                sa += sm_red[g * 1024 + tid + 512];
                sb += sm_red[(g + 1) * 1024 + tid + 512];
            }
            s2 = sa + sb;
        }

        // --- fused epilogue: bias + P gather + tanh -------------------------
        int xid1 = __ldg(&X[myn1 * LEN + t]);
        int xid2 = __ldg(&X[myn2 * LEN + t]);
        float p1 = __ldg(&g_P[(size_t)xid1 * HID + h0 + lane]);
        float p2 = __ldg(&g_P[(size_t)xid2 * HID + h0 + lane]);

        dst[(size_t)myn1 * HID + h0 + lane] = tanhf(s1 + bb + p1);
        dst[(size_t)myn2 * HID + h0 + lane] = tanhf(s2 + bb + p2);

        // --- grid barrier (skip after last step) ----------------------------
        if (t < LEN - 1) {
            __syncthreads();
            if (tid == 0) {
                __threadfence();
                unsigned target = gen0 + (unsigned)t + 1;
                unsigned old = atomicAdd(&g_bar_count, 1u);
                if (old == GRID - 1) {
                    *(volatile unsigned*)&g_bar_count = 0;
                    asm volatile("st.release.gpu.u32 [%0], %1;"
                                 :: "l"(&g_bar_gen), "r"(target) : "memory");
                } else {
                    unsigned g;
                    do {
                        asm volatile("ld.acquire.gpu.u32 %0, [%1];"
                                     : "=r"(g) : "l"(&g_bar_gen) : "memory");
                    } while ((int)(g - target) < 0);
                }
            }
            __syncthreads();
        }
    }
}

// ---------------------------------------------------------------------------
extern "C" void kernel_launch(void* const* d_in, const int* in_sizes, int n_in,
                              void* d_out, int out_size) {
    const int*   X     = (const int*)d_in[0];
    const float* emb   = (const float*)d_in[1];
    const float* Whh_w = (const float*)d_in[2];
    const float* Whh_b = (const float*)d_in[3];
    const float* Wxh_w = (const float*)d_in[4];
    const float* Wxh_b = (const float*)d_in[5];
    float* out = (float*)d_out;

    const size_t sm_proj = (size_t)(64 * (EMB + 4) + 8 * 32 * 36) * sizeof(float); // ~101 KB
    const size_t sm_rnn  = (size_t)(32 * 1024) * sizeof(float);                    // 128 KB
    cudaFuncSetAttribute(proj_kernel, cudaFuncAttributeMaxDynamicSharedMemorySize, (int)sm_proj);
    cudaFuncSetAttribute(rnn_kernel,  cudaFuncAttributeMaxDynamicSharedMemorySize, (int)sm_rnn);

    // 1) P = emb @ Wxh^T + Wxh_b
    proj_kernel<<<dim3(VOCAB / 32, HID / 32), 256, sm_proj>>>(emb, Wxh_w, Wxh_b);

    // 2) all 512 timesteps in one persistent launch
    rnn_kernel<<<GRID, NTHR, sm_rnn>>>(X, Whh_w, Whh_b, out);
}